// round 3
// baseline (speedup 1.0000x reference)
#include <cuda_runtime.h>
#include <math.h>

#define NB     256
#define NPB    65536
#define NBATCH 4
#define EPS    1e-10f
#define INV_N  (1.0f / 65536.0f)
#define GRID   256          // CTAs; all resident in wave 1 -> spin barrier safe
#define TPB    256

// ---------- persistent scratch (zero-init at load; re-zeroed every call) ----------
__device__ float  g_joint[NBATCH * NB * NB];   // 1 MB
__device__ float  g_h1[NBATCH * NB];
__device__ float  g_h2[NBATCH * NB];
__device__ double g_sj[NBATCH];                // joint sum
__device__ double g_ej[NBATCH];                // sum j*log2(j+eps)
__device__ float  g_H1[NBATCH], g_H2[NBATCH];
__device__ volatile unsigned g_bar0;           // grid barrier
__device__ unsigned g_bar1;                    // last-block ticket

// float block reduction over 256 threads
__device__ __forceinline__ float fred256(float v, float* sred) {
#pragma unroll
    for (int o = 16; o; o >>= 1) v += __shfl_xor_sync(0xffffffffu, v, o);
    int wid = threadIdx.x >> 5, lid = threadIdx.x & 31;
    if (lid == 0) sred[wid] = v;
    __syncthreads();
    float r = 0.0f;
    if (threadIdx.x < 32) {
        r = (threadIdx.x < 8) ? sred[threadIdx.x] : 0.0f;
#pragma unroll
        for (int o = 4; o; o >>= 1) r += __shfl_xor_sync(0xffffffffu, r, o);
        if (threadIdx.x == 0) sred[0] = r;
    }
    __syncthreads();
    float out = sred[0];
    __syncthreads();
    return out;
}

__global__ __launch_bounds__(TPB)
void mi_fused_kernel(const float* __restrict__ in1, const float* __restrict__ in2,
                     float* __restrict__ out) {
    __shared__ float sh1[NB];
    __shared__ float sh2[NB];
    __shared__ float sred[8];
    int tid = threadIdx.x;
    int blk = blockIdx.x;

    // ================= phase A: sparse KDE accumulation =================
    // sigma=0.1 in bin units: only the two straddling bins matter (others
    // are <= e^-50 relative).
    sh1[tid] = 0.0f;
    sh2[tid] = 0.0f;
    __syncthreads();

    int base = blk * 1024;                 // 1024 pixels per CTA
    int b = base / NPB;
    float* __restrict__ joint = g_joint + b * NB * NB;

    float4 a = ((const float4*)(in1 + base))[tid];
    float4 c = ((const float4*)(in2 + base))[tid];
    const float xs1[4] = {a.x, a.y, a.z, a.w};
    const float xs2[4] = {c.x, c.y, c.z, c.w};

#pragma unroll
    for (int k = 0; k < 4; k++) {
        float x1 = xs1[k] * 255.0f;
        float x2 = xs2[k] * 255.0f;
        int i0 = min((int)floorf(x1), NB - 2);
        int j0 = min((int)floorf(x2), NB - 2);
        float f1 = x1 - (float)i0, q1 = 1.0f - f1;
        float f2 = x2 - (float)j0, q2 = 1.0f - f2;
        float wa1 = __expf(-50.0f * f1 * f1);
        float wb1 = __expf(-50.0f * q1 * q1);
        float wa2 = __expf(-50.0f * f2 * f2);
        float wb2 = __expf(-50.0f * q2 * q2);

        atomicAdd(&sh1[i0],     wa1);
        atomicAdd(&sh1[i0 + 1], wb1);
        atomicAdd(&sh2[j0],     wa2);
        atomicAdd(&sh2[j0 + 1], wb2);

        float* row = joint + i0 * NB + j0;
        atomicAdd(row,          wa1 * wa2);
        atomicAdd(row + 1,      wa1 * wb2);
        atomicAdd(row + NB,     wb1 * wa2);
        atomicAdd(row + NB + 1, wb1 * wb2);
    }

    __syncthreads();
    atomicAdd(&g_h1[b * NB + tid], sh1[tid]);
    atomicAdd(&g_h2[b * NB + tid], sh2[tid]);

    // ================= grid barrier (all 256 CTAs resident) =================
    __threadfence();
    __syncthreads();
    if (tid == 0) {
        atomicAdd((unsigned*)&g_bar0, 1u);
        while (g_bar0 < (unsigned)GRID) { }
    }
    __syncthreads();

    // ================= phase B: reduce (float hot path) =================
    // 256 CTAs, each owns 1024 joint entries of batch rb = blk/64.
    int rb  = blk >> 6;                    // batch
    int sub = blk & 63;                    // 64 sub-blocks per batch
    float4* j4 = (float4*)(g_joint + rb * NB * NB + sub * 1024);
    float4 j = __ldcg(&j4[tid]);
    float sj = (j.x + j.y) + (j.z + j.w);
    float ej = j.x * __log2f(j.x + EPS)
             + j.y * __log2f(j.y + EPS)
             + j.z * __log2f(j.z + EPS)
             + j.w * __log2f(j.w + EPS);
    j4[tid] = make_float4(0.0f, 0.0f, 0.0f, 0.0f);    // re-zero for next call

    sj = fred256(sj, sred);
    ej = fred256(ej, sred);
    if (tid == 0) {
        atomicAdd(&g_sj[rb], (double)sj);
        atomicAdd(&g_ej[rb], (double)ej);
    }

    // marginals: exact reference math, one CTA per batch
    if (sub == 0) {
        float h1 = __ldcg(&g_h1[rb * NB + tid]);
        float h2 = __ldcg(&g_h2[rb * NB + tid]);
        g_h1[rb * NB + tid] = 0.0f;                   // re-zero
        g_h2[rb * NB + tid] = 0.0f;
        float m1 = h1 * INV_N;
        float m2 = h2 * INV_N;
        float S1 = fred256(m1, sred);
        float S2 = fred256(m2, sred);
        float p1 = m1 / (S1 + EPS);
        float p2 = m2 / (S2 + EPS);
        float e1 = fred256(p1 * __log2f(p1 + EPS), sred);
        float e2 = fred256(p2 * __log2f(p2 + EPS), sred);
        if (tid == 0) { g_H1[rb] = -e1; g_H2[rb] = -e2; }
    }

    // ================= last-block combine + reset =================
    __threadfence();
    __syncthreads();
    if (tid == 0) {
        unsigned t = atomicAdd(&g_bar1, 1u);
        if (t == (unsigned)(GRID - 1)) {
            __threadfence();
            double acc = 0.0;
#pragma unroll
            for (int bb = 0; bb < NBATCH; bb++) {
                double Sj = g_sj[bb];
                double Ej = g_ej[bb];
                double den = Sj + (double)EPS;
                // Hj = -sum q*log2(q+eps), q=j/(Sj+eps), factored single-pass
                double Hj = -(Ej - Sj * log2(den)) / den;
                double H1 = (double)g_H1[bb];
                double H2 = (double)g_H2[bb];
                acc += 2.0 * (H1 + H2 - Hj) / (H1 + H2);
                g_sj[bb] = 0.0; g_ej[bb] = 0.0;
                g_H1[bb] = 0.0f; g_H2[bb] = 0.0f;
            }
            out[0] = (float)(acc * 0.25);
            g_bar1 = 0u;
            *(unsigned*)&g_bar0 = 0u;     // reset grid barrier for next replay
        }
    }
}

extern "C" void kernel_launch(void* const* d_in, const int* in_sizes, int n_in,
                              void* d_out, int out_size) {
    const float* in1 = (const float*)d_in[0];
    const float* in2 = (const float*)d_in[1];
    mi_fused_kernel<<<GRID, TPB>>>(in1, in2, (float*)d_out);
}

// round 4
// speedup vs baseline: 1.0699x; 1.0699x over previous
#include <cuda_runtime.h>
#include <math.h>

#define NB     256
#define NPB    65536
#define NBATCH 4
#define EPS    1e-10f
#define INV_N  (1.0f / 65536.0f)

// ---------- persistent scratch (zero-init at load; re-zeroed every call) ----------
__device__ float  g_joint[NBATCH * NB * NB];   // 1 MB
__device__ float  g_h1[NBATCH * NB];
__device__ float  g_h2[NBATCH * NB];
__device__ double g_sj[NBATCH];                // joint sum
__device__ double g_ej[NBATCH];                // sum j*log2(j+eps)
__device__ float  g_H1[NBATCH], g_H2[NBATCH];
__device__ unsigned g_bar1;                    // last-block ticket

// ================= kernel 1: sparse KDE accumulation =================
// sigma=0.1 in bin units (bins 1.0 apart): weight beyond the two straddling
// bins is <= e^-50 ~ 2e-22 relative -> truncate to 2 bins per pixel.
#define THREADS_ACC 256
#define PIX_PER_CTA 1024     // THREADS_ACC * 4 (one float4 per thread)

__global__ __launch_bounds__(THREADS_ACC)
void mi_accum_kernel(const float* __restrict__ in1, const float* __restrict__ in2) {
    __shared__ float sh1[NB];
    __shared__ float sh2[NB];
    int tid = threadIdx.x;
    sh1[tid] = 0.0f;
    sh2[tid] = 0.0f;
    __syncthreads();

    int base = blockIdx.x * PIX_PER_CTA;
    int b = base / NPB;
    float* __restrict__ joint = g_joint + b * NB * NB;

    float4 a = ((const float4*)(in1 + base))[tid];
    float4 c = ((const float4*)(in2 + base))[tid];
    const float xs1[4] = {a.x, a.y, a.z, a.w};
    const float xs2[4] = {c.x, c.y, c.z, c.w};

#pragma unroll
    for (int k = 0; k < 4; k++) {
        float x1 = xs1[k] * 255.0f;
        float x2 = xs2[k] * 255.0f;
        int i0 = min((int)floorf(x1), NB - 2);
        int j0 = min((int)floorf(x2), NB - 2);
        float f1 = x1 - (float)i0, q1 = 1.0f - f1;
        float f2 = x2 - (float)j0, q2 = 1.0f - f2;
        float wa1 = __expf(-50.0f * f1 * f1);
        float wb1 = __expf(-50.0f * q1 * q1);
        float wa2 = __expf(-50.0f * f2 * f2);
        float wb2 = __expf(-50.0f * q2 * q2);

        atomicAdd(&sh1[i0],     wa1);
        atomicAdd(&sh1[i0 + 1], wb1);
        atomicAdd(&sh2[j0],     wa2);
        atomicAdd(&sh2[j0 + 1], wb2);

        float* row = joint + i0 * NB + j0;
        atomicAdd(row,          wa1 * wa2);
        atomicAdd(row + 1,      wa1 * wb2);
        atomicAdd(row + NB,     wb1 * wa2);
        atomicAdd(row + NB + 1, wb1 * wb2);
    }

    __syncthreads();
    atomicAdd(&g_h1[b * NB + tid], sh1[tid]);
    atomicAdd(&g_h2[b * NB + tid], sh2[tid]);
}

// ================= kernel 2: wide float reduce + combine + re-zero =================
// 256 CTAs x 256 thr. Each CTA: 1024 joint entries of batch blk/64, single
// pass (sum + sum j*log2(j+eps)), re-zero, double atomic partials. CTA sub==0
// of each batch does exact marginal entropies. Last CTA combines -> d_out.
__device__ __forceinline__ float fred256(float v, float* sred) {
#pragma unroll
    for (int o = 16; o; o >>= 1) v += __shfl_xor_sync(0xffffffffu, v, o);
    int wid = threadIdx.x >> 5, lid = threadIdx.x & 31;
    if (lid == 0) sred[wid] = v;
    __syncthreads();
    float r = 0.0f;
    if (threadIdx.x < 32) {
        r = (threadIdx.x < 8) ? sred[threadIdx.x] : 0.0f;
#pragma unroll
        for (int o = 4; o; o >>= 1) r += __shfl_xor_sync(0xffffffffu, r, o);
        if (threadIdx.x == 0) sred[0] = r;
    }
    __syncthreads();
    float out = sred[0];
    __syncthreads();
    return out;
}

__global__ __launch_bounds__(256)
void mi_reduce_final_kernel(float* __restrict__ out) {
    __shared__ float sred[8];
    int tid = threadIdx.x;
    int rb  = blockIdx.x >> 6;             // batch
    int sub = blockIdx.x & 63;             // 64 sub-slices per batch

    float4* j4 = (float4*)(g_joint + rb * NB * NB + sub * 1024);
    float4 j = __ldcg(&j4[tid]);
    float sj = (j.x + j.y) + (j.z + j.w);
    float ej = j.x * __log2f(j.x + EPS)
             + j.y * __log2f(j.y + EPS)
             + j.z * __log2f(j.z + EPS)
             + j.w * __log2f(j.w + EPS);
    j4[tid] = make_float4(0.0f, 0.0f, 0.0f, 0.0f);   // re-zero for next replay

    sj = fred256(sj, sred);
    ej = fred256(ej, sred);
    if (tid == 0) {
        atomicAdd(&g_sj[rb], (double)sj);
        atomicAdd(&g_ej[rb], (double)ej);
    }

    // marginals: exact reference math, one CTA per batch
    if (sub == 0) {
        float h1 = __ldcg(&g_h1[rb * NB + tid]);
        float h2 = __ldcg(&g_h2[rb * NB + tid]);
        g_h1[rb * NB + tid] = 0.0f;                   // re-zero
        g_h2[rb * NB + tid] = 0.0f;
        float m1 = h1 * INV_N;
        float m2 = h2 * INV_N;
        float S1 = fred256(m1, sred);
        float S2 = fred256(m2, sred);
        float p1 = m1 / (S1 + EPS);
        float p2 = m2 / (S2 + EPS);
        float e1 = fred256(p1 * __log2f(p1 + EPS), sred);
        float e2 = fred256(p2 * __log2f(p2 + EPS), sred);
        if (tid == 0) { g_H1[rb] = -e1; g_H2[rb] = -e2; }
    }

    // last-block combine + reset of cross-call state
    __threadfence();
    __syncthreads();
    if (tid == 0) {
        unsigned t = atomicAdd(&g_bar1, 1u);
        if (t == 255u) {
            __threadfence();
            double acc = 0.0;
#pragma unroll
            for (int bb = 0; bb < NBATCH; bb++) {
                double Sj = g_sj[bb];
                double Ej = g_ej[bb];
                double den = Sj + (double)EPS;
                // Hj = -sum q*log2(q+eps), q=j/(Sj+eps), factored single-pass
                double Hj = -(Ej - Sj * log2(den)) / den;
                double H1 = (double)g_H1[bb];
                double H2 = (double)g_H2[bb];
                acc += 2.0 * (H1 + H2 - Hj) / (H1 + H2);
                g_sj[bb] = 0.0; g_ej[bb] = 0.0;
                g_H1[bb] = 0.0f; g_H2[bb] = 0.0f;
            }
            out[0] = (float)(acc * 0.25);
            g_bar1 = 0u;
        }
    }
}

// ================= launch: 2 kernels =================
extern "C" void kernel_launch(void* const* d_in, const int* in_sizes, int n_in,
                              void* d_out, int out_size) {
    const float* in1 = (const float*)d_in[0];
    const float* in2 = (const float*)d_in[1];
    float* out = (float*)d_out;

    mi_accum_kernel<<<(NBATCH * NPB) / PIX_PER_CTA, THREADS_ACC>>>(in1, in2);
    mi_reduce_final_kernel<<<256, 256>>>(out);
}